// round 17
// baseline (speedup 1.0000x reference)
#include <cuda_runtime.h>
#include <cuda_fp16.h>
#include <cstdint>

#define Bb  8
#define Ss  2048
#define Dd  256
#define DOo 256
#define Ll  8
#define Ee  32768

// ---- static device scratch ----
__device__ __align__(128) __half g_y[(size_t)Bb * Ll * Ss * DOo];  // 64 MiB (fp16 Y)
// X in MMA A-fragment order: [mblock(1024)][kstep(16)][lane(32)][reg(4)][h(2)]
__device__ __align__(128) __half g_xfrag[(size_t)Bb * Ss * Dd];    // 8 MiB
// W in MMA B-fragment order: [(l*16+nb16)*16+kstep][lane][4 regs][2 halves]
__device__ __align__(128) __half g_wfrag[(size_t)Ll * 16 * 16 * 256];  // 1 MiB
__device__ int g_deg[Bb * Ss];
__device__ int g_offs[Bb * Ss + 1];
__device__ int g_cursor[Bb * Ss];
__device__ int g_perm[Bb * Ee];                                    // l*Ss + s

// ---- streams + events + symbol addr, created once at process init ----
static cudaStream_t g_s2 = nullptr;
static cudaEvent_t g_ev0 = nullptr, g_ev1 = nullptr;
static cudaEvent_t g_evH0 = nullptr, g_evH1 = nullptr, g_evP1 = nullptr;
static void* g_deg_ptr = nullptr;
static bool g_streams_ok = false;
namespace {
struct _StreamInit {
    _StreamInit() {
        bool ok = true;
        ok &= (cudaStreamCreateWithFlags(&g_s2, cudaStreamNonBlocking) == cudaSuccess);
        ok &= (cudaEventCreateWithFlags(&g_ev0, cudaEventDisableTiming) == cudaSuccess);
        ok &= (cudaEventCreateWithFlags(&g_ev1, cudaEventDisableTiming) == cudaSuccess);
        ok &= (cudaEventCreateWithFlags(&g_evH0, cudaEventDisableTiming) == cudaSuccess);
        ok &= (cudaEventCreateWithFlags(&g_evH1, cudaEventDisableTiming) == cudaSuccess);
        ok &= (cudaEventCreateWithFlags(&g_evP1, cudaEventDisableTiming) == cudaSuccess);
        ok &= (cudaGetSymbolAddress(&g_deg_ptr, g_deg) == cudaSuccess);
        g_streams_ok = ok;
    }
} _stream_init;
}

// ================= CSR-build kernels =================
__global__ void k_zero_deg() {
    int i = blockIdx.x * blockDim.x + threadIdx.x;
    if (i < Bb * Ss) g_deg[i] = 0;
}
__global__ void k_hist(const int* __restrict__ tgt) {
    int i = blockIdx.x * blockDim.x + threadIdx.x;
    if (i < Bb * Ee) {
        int b = i / Ee;
        atomicAdd(&g_deg[b * Ss + tgt[i]], 1);
    }
}
__global__ void k_scan() {
    const int t = threadIdx.x;
    const int base = t * 16;
    int loc[16]; int sum = 0;
#pragma unroll
    for (int i = 0; i < 16; i++) { loc[i] = sum; sum += g_deg[base + i]; }
    int lane = t & 31, warp = t >> 5;
    int v = sum;
#pragma unroll
    for (int o = 1; o < 32; o <<= 1) {
        int u = __shfl_up_sync(0xFFFFFFFF, v, o);
        if (lane >= o) v += u;
    }
    __shared__ int wsum[32];
    if (lane == 31) wsum[warp] = v;
    __syncthreads();
    if (warp == 0) {
        int w = wsum[lane];
#pragma unroll
        for (int o = 1; o < 32; o <<= 1) {
            int u = __shfl_up_sync(0xFFFFFFFF, w, o);
            if (lane >= o) w += u;
        }
        wsum[lane] = w;
    }
    __syncthreads();
    int pre = v - sum + (warp ? wsum[warp - 1] : 0);
#pragma unroll
    for (int i = 0; i < 16; i++) {
        int o = pre + loc[i];
        g_offs[base + i]   = o;
        g_cursor[base + i] = o;
    }
    if (t == 1023) g_offs[Bb * Ss] = wsum[31];
}
__global__ void k_fill(const int* __restrict__ tgt, const int* __restrict__ lab,
                       const int* __restrict__ src) {
    int i = blockIdx.x * blockDim.x + threadIdx.x;
    if (i < Bb * Ee) {
        int b = i / Ee;
        int pos = atomicAdd(&g_cursor[b * Ss + tgt[i]], 1);
        g_perm[pos] = lab[i] * Ss + src[i];
    }
}

// ================= prep kernels: fp32 -> fp16 fragment layouts (vectorized) =====
__device__ __forceinline__ void store_a_frag2(int m_g, int k2, float2 v) {
    int row = m_g & 15, mb = m_g >> 4;
    int ks = k2 >> 4, kk = k2 & 15;
    int lane = ((row & 7) << 2) + ((kk & 7) >> 1);
    int reg  = (((kk >> 3) & 1) << 1) + ((row >> 3) & 1);
    size_t pos = ((size_t)mb * 16 + ks) * 256 + lane * 8 + reg * 2;
    *reinterpret_cast<__half2*>(&g_xfrag[pos]) = __float22half2_rn(v);
}
// prep0: W + X batches 0-4 (5 batches)
__global__ void k_prep0(const float* __restrict__ X, const float* __restrict__ W) {
    int i = blockIdx.x * blockDim.x + threadIdx.x;
    if (i < 5 * Ss * Dd / 2) {
        int e = 2 * i;
        float2 v = *reinterpret_cast<const float2*>(X + e);
        store_a_frag2(e >> 8, e & 255, v);
    }
    if (i < Ll * Dd * DOo / 2) {
#pragma unroll
        for (int t = 0; t < 2; t++) {
            int j = i * 2 + t;
            int l = j / (Dd * DOo);
            int r = j - l * (Dd * DOo);
            int k = r >> 8;
            int n = r & 255;
            int nb   = n >> 4;
            int reg  = (((n >> 3) & 1) << 1) + ((k & 15) >> 3);
            int lane = ((n & 7) << 2) + ((k & 7) >> 1);
            int h    = k & 1;
            size_t pos = ((size_t)((l * 16 + nb) * 16 + (k >> 4))) * 256
                       + lane * 8 + reg * 2 + h;
            g_wfrag[pos] = __float2half(W[j]);
        }
    }
}
// prep1: X batches 5-7 (3 batches)
__global__ void k_prep1(const float* __restrict__ X) {
    int i = blockIdx.x * blockDim.x + threadIdx.x;
    if (i < 3 * Ss * Dd / 2) {
        int e = 5 * Ss * Dd + 2 * i;
        float2 v = *reinterpret_cast<const float2*>(X + e);
        store_a_frag2(e >> 8, e & 255, v);
    }
}

// ================= fp16 mma.sync GEMM: fragment-LDG, A+B double-buffered ========
__device__ __forceinline__ void mma16816(float* c, const uint32_t* a,
                                         uint32_t b0, uint32_t b1) {
    asm volatile(
        "mma.sync.aligned.m16n8k16.row.col.f32.f16.f16.f32 "
        "{%0,%1,%2,%3}, {%4,%5,%6,%7}, {%8,%9}, {%0,%1,%2,%3};"
        : "+f"(c[0]), "+f"(c[1]), "+f"(c[2]), "+f"(c[3])
        : "r"(a[0]), "r"(a[1]), "r"(a[2]), "r"(a[3]), "r"(b0), "r"(b1));
}

// grid: (Ss/128, DOo/128, nb*Ll); batch = b_base + z>>3, label = z&7
__global__ __launch_bounds__(256, 2) void k_gemm_mma(const float* __restrict__ bias,
                                                     int b_base) {
    const int tid = threadIdx.x;
    const int lane = tid & 31;
    const int wid = tid >> 5;
    const int warp_m = wid & 1;                // 2 x 64 rows
    const int warp_n = wid >> 1;               // 4 x 32 cols
    const int z = blockIdx.z;
    const int b = b_base + (z >> 3);
    const int l = z & 7;
    const int bl = b * Ll + l;
    const int m0 = blockIdx.x * 128;
    const int n0 = blockIdx.y * 128;

    const __half* Af = g_xfrag
        + ((size_t)((b * Ss + m0) >> 4) + warp_m * 4) * 4096 + lane * 8;
    const int nb0 = (n0 >> 4) + warp_n * 2;
    const __half* Bf0 = g_wfrag + (size_t)(l * 16 + nb0) * 4096 + lane * 8;
    const __half* Bf1 = Bf0 + 4096;

    float acc[4][4][4];
#pragma unroll
    for (int i = 0; i < 4; i++)
#pragma unroll
        for (int j = 0; j < 4; j++)
#pragma unroll
            for (int q = 0; q < 4; q++) acc[i][j][q] = 0.f;

    // double-buffer both A and B: prefetch kstep+1 while MMAing kstep
    uint4 b0c = *reinterpret_cast<const uint4*>(Bf0);
    uint4 b1c = *reinterpret_cast<const uint4*>(Bf1);
    uint4 av[4];
#pragma unroll
    for (int im = 0; im < 4; im++)
        av[im] = *reinterpret_cast<const uint4*>(Af + im * 4096);

#pragma unroll
    for (int ks = 0; ks < 16; ks++) {
        uint4 b0n, b1n, avn[4];
        if (ks < 15) {
            b0n = *reinterpret_cast<const uint4*>(Bf0 + (ks + 1) * 256);
            b1n = *reinterpret_cast<const uint4*>(Bf1 + (ks + 1) * 256);
#pragma unroll
            for (int im = 0; im < 4; im++)
                avn[im] = *reinterpret_cast<const uint4*>(Af + im * 4096 + (ks + 1) * 256);
        }

        const uint32_t* p0 = reinterpret_cast<const uint32_t*>(&b0c);
        const uint32_t* p1 = reinterpret_cast<const uint32_t*>(&b1c);
#pragma unroll
        for (int im = 0; im < 4; im++) {
            const uint32_t* a = reinterpret_cast<const uint32_t*>(&av[im]);
            mma16816(acc[im][0], a, p0[0], p0[1]);
            mma16816(acc[im][1], a, p0[2], p0[3]);
            mma16816(acc[im][2], a, p1[0], p1[1]);
            mma16816(acc[im][3], a, p1[2], p1[3]);
        }
        if (ks < 15) {
            b0c = b0n; b1c = b1n;
#pragma unroll
            for (int im = 0; im < 4; im++) av[im] = avn[im];
        }
    }

    // epilogue: Y = half(acc + bias)
    __half* Yb = g_y + (size_t)bl * Ss * DOo;
    const float* bp = bias + l * DOo;
#pragma unroll
    for (int im = 0; im < 4; im++) {
        int m = m0 + warp_m * 64 + im * 16 + (lane >> 2);
#pragma unroll
        for (int in = 0; in < 4; in++) {
            int n = n0 + warp_n * 32 + in * 8 + 2 * (lane & 3);
            float bx = bp[n], by = bp[n + 1];
            float2 f0 = { acc[im][in][0] + bx, acc[im][in][1] + by };
            float2 f1 = { acc[im][in][2] + bx, acc[im][in][3] + by };
            __half2 h0 = __float22half2_rn(f0);
            __half2 h1 = __float22half2_rn(f1);
            *reinterpret_cast<__half2*>(Yb + (size_t)m * DOo + n) = h0;
            *reinterpret_cast<__half2*>(Yb + (size_t)(m + 8) * DOo + n) = h1;
        }
    }
}

// ================= gather-reduce + ReLU: warp per row, ILP-8 LDG.128 ===========
__global__ __launch_bounds__(256) void k_gather(float* __restrict__ out, int b_base) {
    const int warp = threadIdx.x >> 5;
    const int lane = threadIdx.x & 31;
    const int r = b_base * Ss + blockIdx.x * 8 + warp;
    const int b = r >> 11;
    const int co = lane * 8;
    const int beg = g_offs[r];
    const int end = g_offs[r + 1];
    const __half* Yb = g_y + (size_t)b * Ll * Ss * DOo;

    float acc0[8] = {0,0,0,0,0,0,0,0};
    float acc1[8] = {0,0,0,0,0,0,0,0};

#define ACC8(acc, v) do {                                                        \
    float2 t0 = __half22float2(*reinterpret_cast<const __half2*>(&(v).x));       \
    float2 t1 = __half22float2(*reinterpret_cast<const __half2*>(&(v).y));       \
    float2 t2 = __half22float2(*reinterpret_cast<const __half2*>(&(v).z));       \
    float2 t3 = __half22float2(*reinterpret_cast<const __half2*>(&(v).w));       \
    acc[0] += t0.x; acc[1] += t0.y; acc[2] += t1.x; acc[3] += t1.y;              \
    acc[4] += t2.x; acc[5] += t2.y; acc[6] += t3.x; acc[7] += t3.y;              \
} while (0)

    int i = beg;
    for (; i + 7 < end; i += 8) {
        int p[8];
#pragma unroll
        for (int j = 0; j < 8; j++) p[j] = __ldg(&g_perm[i + j]);
        uint4 v[8];
#pragma unroll
        for (int j = 0; j < 8; j++)
            v[j] = *reinterpret_cast<const uint4*>(Yb + (size_t)p[j] * DOo + co);
#pragma unroll
        for (int j = 0; j < 8; j += 2) {
            ACC8(acc0, v[j]);
            ACC8(acc1, v[j + 1]);
        }
    }
    for (; i + 1 < end; i += 2) {
        int p0 = __ldg(&g_perm[i]);
        int p1 = __ldg(&g_perm[i + 1]);
        uint4 v0 = *reinterpret_cast<const uint4*>(Yb + (size_t)p0 * DOo + co);
        uint4 v1 = *reinterpret_cast<const uint4*>(Yb + (size_t)p1 * DOo + co);
        ACC8(acc0, v0);
        ACC8(acc1, v1);
    }
    if (i < end) {
        uint4 v = *reinterpret_cast<const uint4*>(
            Yb + (size_t)__ldg(&g_perm[i]) * DOo + co);
        ACC8(acc0, v);
    }
#undef ACC8

    float* op = out + (size_t)r * DOo + co;
    float4 o0 = { fmaxf(acc0[0] + acc1[0], 0.f), fmaxf(acc0[1] + acc1[1], 0.f),
                  fmaxf(acc0[2] + acc1[2], 0.f), fmaxf(acc0[3] + acc1[3], 0.f) };
    float4 o1 = { fmaxf(acc0[4] + acc1[4], 0.f), fmaxf(acc0[5] + acc1[5], 0.f),
                  fmaxf(acc0[6] + acc1[6], 0.f), fmaxf(acc0[7] + acc1[7], 0.f) };
    *reinterpret_cast<float4*>(op)     = o0;
    *reinterpret_cast<float4*>(op + 4) = o1;
}

// ================= launch =================
extern "C" void kernel_launch(void* const* d_in, const int* in_sizes, int n_in,
                              void* d_out, int out_size) {
    const float* X    = (const float*)d_in[0];
    const int*   esrc = (const int*)d_in[1];
    const int*   etgt = (const int*)d_in[2];
    const int*   elab = (const int*)d_in[3];
    const float* W    = (const float*)d_in[4];
    const float* bias = (const float*)d_in[5];
    float* out = (float*)d_out;

    // 5/3 asymmetric batch split
    dim3 ggrid0(Ss / 128, DOo / 128, 5 * Ll);      // batches 0-4: 1280 CTAs
    dim3 ggrid1(Ss / 128, DOo / 128, 3 * Ll);      // batches 5-7:  768 CTAs
    const int PREP0_TH = 5 * Ss * Dd / 2;
    const int PREP1_TH = 3 * Ss * Dd / 2;

    if (g_streams_ok) {
        cudaEventRecord(g_ev0, 0);
        cudaStreamWaitEvent(g_s2, g_ev0, 0);

        // side: CSR start
        cudaMemsetAsync(g_deg_ptr, 0, Bb * Ss * sizeof(int), g_s2);
        k_hist<<<(Bb * Ee + 255) / 256, 256, 0, g_s2>>>(etgt);

        // main: prep0, gemmH0 (profiled slot)
        k_prep0<<<(PREP0_TH + 255) / 256, 256>>>(X, W);
        k_gemm_mma<<<ggrid0, 256>>>(bias, 0);              // batches 0-4
        cudaEventRecord(g_evH0, 0);

        // side: prep half1 (under gemmH0), then CSR finish
        k_prep1<<<(PREP1_TH + 255) / 256, 256, 0, g_s2>>>(X);
        cudaEventRecord(g_evP1, g_s2);
        k_scan<<<1, 1024, 0, g_s2>>>();
        k_fill<<<(Bb * Ee + 255) / 256, 256, 0, g_s2>>>(etgt, elab, esrc);

        // main: gemmH1 after prep1
        cudaStreamWaitEvent(0, g_evP1, 0);
        k_gemm_mma<<<ggrid1, 256>>>(bias, 5);              // batches 5-7
        cudaEventRecord(g_evH1, 0);

        // side: gathers
        cudaStreamWaitEvent(g_s2, g_evH0, 0);
        k_gather<<<5 * Ss / 8, 256, 0, g_s2>>>(out, 0);
        cudaStreamWaitEvent(g_s2, g_evH1, 0);
        k_gather<<<3 * Ss / 8, 256, 0, g_s2>>>(out, 5);
        cudaEventRecord(g_ev1, g_s2);
        cudaStreamWaitEvent(0, g_ev1, 0);
    } else {
        k_zero_deg<<<(Bb * Ss + 255) / 256, 256>>>();
        k_hist<<<(Bb * Ee + 255) / 256, 256>>>(etgt);
        k_scan<<<1, 1024>>>();
        k_fill<<<(Bb * Ee + 255) / 256, 256>>>(etgt, elab, esrc);
        k_prep0<<<(PREP0_TH + 255) / 256, 256>>>(X, W);
        k_prep1<<<(PREP1_TH + 255) / 256, 256>>>(X);
        k_gemm_mma<<<ggrid0, 256>>>(bias, 0);
        k_gemm_mma<<<ggrid1, 256>>>(bias, 5);
        k_gather<<<5 * Ss / 8, 256>>>(out, 0);
        k_gather<<<3 * Ss / 8, 256>>>(out, 5);
    }
}